// round 3
// baseline (speedup 1.0000x reference)
#include <cuda_runtime.h>
#include <cstdint>
#include <cstddef>

#define BB 64
#define TT 512
#define EE 256
#define HH 256
#define LLB 9
#define G4 1024   // 4*H

typedef unsigned long long u64;

// Scratch (device globals; no allocations allowed)
// g_xg: [dir][t][col][bp] as f32x2 pairs (b=bp, b=bp+32).  256 MiB
__device__ u64 g_xg[(size_t)2*TT*G4*32];
// g_h: [dir][t][u][bp] as f32x2 pairs.                      64 MiB
__device__ u64 g_h [(size_t)2*TT*HH*32];
__device__ int      g_seqlen[BB];
__device__ unsigned g_barc[2];
__device__ unsigned g_barg[2];

// ---------------- f32x2 helpers ----------------
__device__ __forceinline__ u64 pk2(float x, float y){
    u64 r; asm("mov.b64 %0,{%1,%2};" : "=l"(r) : "f"(x), "f"(y)); return r;
}
__device__ __forceinline__ void upk2(u64 v, float& x, float& y){
    asm("mov.b64 {%0,%1},%2;" : "=f"(x), "=f"(y) : "l"(v));
}
__device__ __forceinline__ u64 fma2(u64 a, u64 b, u64 c){
    u64 d; asm("fma.rn.f32x2 %0,%1,%2,%3;" : "=l"(d) : "l"(a), "l"(b), "l"(c)); return d;
}

__device__ __forceinline__ float sigf(float x){
    return __fdividef(1.f, 1.f + __expf(-x));
}
__device__ __forceinline__ float tanhfast(float x){
    return 1.f - __fdividef(2.f, __expf(2.f*x) + 1.f);
}

// ---------------------------------------------------------------- seq_len
__global__ void k_seqlen(const int* __restrict__ tokens, float* __restrict__ out_seq){
    int b = blockIdx.x, tid = threadIdx.x;
    int cnt = 0;
    for (int t = tid; t < TT; t += blockDim.x)
        cnt += (tokens[b*TT + t] != 0);
    __shared__ int sred[128];
    sred[tid] = cnt; __syncthreads();
    for (int s = 64; s > 0; s >>= 1){
        if (tid < s) sred[tid] += sred[tid+s];
        __syncthreads();
    }
    if (tid == 0){ g_seqlen[b] = sred[0]; out_seq[b] = (float)sred[0]; }
}

__global__ void k_init(){
    if (threadIdx.x < 2){ g_barc[threadIdx.x] = 0u; g_barg[threadIdx.x] = 0u; }
}

// ---------------------------------------------------------------- xg GEMM (f32x2)
// out[t, col, bp] (f32x2 over batches bp,bp+32) = emb[tok] @ Wx + bias
// grid (512 t, 32 ct: 16 fwd + 16 bwd), block 256
__global__ void __launch_bounds__(256) k_xg(
    const int* __restrict__ tokens, const float* __restrict__ emb,
    const float* __restrict__ Wxf, const float* __restrict__ bf,
    const float* __restrict__ Wxb, const float* __restrict__ bb_)
{
    extern __shared__ float sm[];
    float* As = sm;            // [256 k][64 b]   64KB
    float* Ws = sm + 16384;    // [256 k][64 c]   64KB
    float* tr = sm;            // transpose buffer reuses As: [64 c][65]
    __shared__ int toks[64];

    int t    = blockIdx.x;
    int ct   = blockIdx.y;
    int dir  = ct >> 4;
    int col0 = (ct & 15) * 64;
    const float* Wx   = dir ? Wxb : Wxf;
    const float* bias = dir ? bb_ : bf;
    int tid = threadIdx.x;

    if (tid < 64) toks[tid] = tokens[tid*TT + t];
    __syncthreads();

    for (int i = tid; i < 4096; i += 256){
        int b = i & 63, k4 = i >> 6;
        float4 v = *(const float4*)(emb + (size_t)toks[b]*EE + k4*4);
        As[(k4*4+0)*64 + b] = v.x;
        As[(k4*4+1)*64 + b] = v.y;
        As[(k4*4+2)*64 + b] = v.z;
        As[(k4*4+3)*64 + b] = v.w;
    }
    for (int i = tid; i < 4096; i += 256){
        int k = i >> 4, c4 = i & 15;
        float4 v = *(const float4*)(Wx + (size_t)k*G4 + col0 + c4*4);
        *(float4*)(Ws + k*64 + c4*4) = v;
    }
    __syncthreads();

    int tx = tid & 15, ty = tid >> 4;   // tx: col quad, ty: batch base
    u64 acc[4][2];
    {
        float b0 = bias[col0 + tx*4 + 0];
        float b1 = bias[col0 + tx*4 + 1];
        float b2 = bias[col0 + tx*4 + 2];
        float b3 = bias[col0 + tx*4 + 3];
        u64 p0 = pk2(b0,b1), p1 = pk2(b2,b3);
        #pragma unroll
        for (int bi = 0; bi < 4; ++bi){ acc[bi][0] = p0; acc[bi][1] = p1; }
    }

    #pragma unroll 4
    for (int k = 0; k < 256; ++k){
        ulonglong2 w = *(const ulonglong2*)(Ws + k*64 + tx*4);  // (w0,w1)(w2,w3)
        float a0 = As[k*64 + ty];
        float a1 = As[k*64 + ty + 16];
        float a2 = As[k*64 + ty + 32];
        float a3 = As[k*64 + ty + 48];
        u64 A0 = pk2(a0,a0), A1 = pk2(a1,a1), A2 = pk2(a2,a2), A3 = pk2(a3,a3);
        acc[0][0] = fma2(A0, w.x, acc[0][0]); acc[0][1] = fma2(A0, w.y, acc[0][1]);
        acc[1][0] = fma2(A1, w.x, acc[1][0]); acc[1][1] = fma2(A1, w.y, acc[1][1]);
        acc[2][0] = fma2(A2, w.x, acc[2][0]); acc[2][1] = fma2(A2, w.y, acc[2][1]);
        acc[3][0] = fma2(A3, w.x, acc[3][0]); acc[3][1] = fma2(A3, w.y, acc[3][1]);
    }
    __syncthreads();   // done reading As; reuse as tr

    #pragma unroll
    for (int bi = 0; bi < 4; ++bi){
        int b = ty + bi*16;
        #pragma unroll
        for (int j = 0; j < 2; ++j){
            float v0, v1; upk2(acc[bi][j], v0, v1);
            int c = tx*4 + 2*j;
            tr[c*65 + b]     = v0;
            tr[(c+1)*65 + b] = v1;
        }
    }
    __syncthreads();

    // store: g_xg float view [ (dir*TT+t)*1024 + col ][ x ] where x=bp*2+comp, b=(x>>1)+32*(x&1)
    float* dst = (float*)g_xg + ((size_t)(dir*TT + t)*G4 + col0) * 64;
    for (int i = tid; i < 4096; i += 256){
        int x = i & 63, c = i >> 6;
        int b = (x >> 1) + ((x & 1) << 5);
        dst[i] = tr[c*65 + b];
    }
}

// ---------------------------------------------------------------- recurrence
// 128 CTAs: [0,64) fwd, [64,128) bwd. CTA owns 4 hidden units.
// 128 threads: bp = tid&31 (batch pair), ul = tid>>5 (unit). All 4 gates per thread.
__device__ __forceinline__ void grid_barrier_dir(int dir, int tid){
    __threadfence();
    __syncthreads();
    if (tid == 0){
        volatile unsigned* vgen = (volatile unsigned*)&g_barg[dir];
        unsigned gen = *vgen;
        unsigned old = atomicAdd(&g_barc[dir], 1u);
        if (old == 63u){
            atomicExch(&g_barc[dir], 0u);
            __threadfence();
            atomicAdd(&g_barg[dir], 1u);
        } else {
            while (*vgen == gen) { }
        }
        __threadfence();
    }
    __syncthreads();
}

__global__ void __launch_bounds__(128) k_recur(
    const float* __restrict__ Whf, const float* __restrict__ Whb)
{
    extern __shared__ u64 smu[];
    u64* hs  = smu;          // [256 k][32 bp]  64KB
    u64* Whs = smu + 8192;   // [256 k][4 ul][4 g] duplicated pairs  32KB

    int cta = blockIdx.x;
    int dir = cta >> 6;
    int u0  = (cta & 63) * 4;
    const float* Wh = dir ? Whb : Whf;
    int tid = threadIdx.x;
    int bp = tid & 31;
    int ul = tid >> 5;
    int u  = u0 + ul;

    for (int i = tid; i < 4096; i += 128){
        int k = i >> 4, q = i & 15;
        int ulx = q >> 2, g = q & 3;
        float w = Wh[(size_t)k*G4 + g*HH + u0 + ulx];
        Whs[i] = pk2(w, w);
    }
    __syncthreads();

    float ca = 0.f, cb = 0.f;
    size_t hdir = (size_t)dir * TT * HH * 32;

    for (int step = 0; step < TT; ++step){
        int t = dir ? (TT-1-step) : step;
        size_t xb = ((size_t)(dir*TT + t) * G4 + u) * 32 + bp;
        u64 acc0 = g_xg[xb];
        u64 acc1 = g_xg[xb + (size_t)1*HH*32];
        u64 acc2 = g_xg[xb + (size_t)2*HH*32];
        u64 acc3 = g_xg[xb + (size_t)3*HH*32];

        if (step > 0){
            int tp = dir ? (t+1) : (t-1);
            const float4* src = (const float4*)(g_h + hdir + (size_t)tp*HH*32);
            float4* dsts = (float4*)hs;
            #pragma unroll
            for (int i = 0; i < 32; ++i) dsts[tid + 128*i] = src[tid + 128*i];
            __syncthreads();

            #pragma unroll 4
            for (int k = 0; k < HH; ++k){
                u64 h2 = hs[k*32 + bp];
                ulonglong2 wA = *(const ulonglong2*)(Whs + k*16 + ul*4);
                ulonglong2 wB = *(const ulonglong2*)(Whs + k*16 + ul*4 + 2);
                acc0 = fma2(h2, wA.x, acc0);
                acc1 = fma2(h2, wA.y, acc1);
                acc2 = fma2(h2, wB.x, acc2);
                acc3 = fma2(h2, wB.y, acc3);
            }
        }

        float ia, ib, fa, fb, ga, gb, oa, ob;
        upk2(acc0, ia, ib);
        upk2(acc1, fa, fb);
        upk2(acc2, ga, gb);
        upk2(acc3, oa, ob);
        ca = sigf(fa)*ca + sigf(ia)*tanhfast(ga);
        cb = sigf(fb)*cb + sigf(ib)*tanhfast(gb);
        float ha = sigf(oa)*tanhfast(ca);
        float hb = sigf(ob)*tanhfast(cb);
        g_h[hdir + (size_t)t*HH*32 + (size_t)u*32 + bp] = pk2(ha, hb);

        grid_barrier_dir(dir, tid);
    }
}

// ---------------------------------------------------------------- dense
// logits[b,t,l] = enc[b,t,:] @ Wd + bd ; enc = [h_fwd | h_bwd] (packed-pair layout)
__global__ void __launch_bounds__(576) k_dense(
    const float* __restrict__ Wd, const float* __restrict__ bd,
    float* __restrict__ out)
{
    extern __shared__ float sm[];
    float* hsf = sm;             // 32768 floats: fwd 16384 + bwd 16384
    float* Wds = sm + 32768;     // 512*9

    int t = blockIdx.x, tid = threadIdx.x;
    const float4* s0 = (const float4*)(g_h + (size_t)t*HH*32);
    const float4* s1 = (const float4*)(g_h + (size_t)(TT + t)*HH*32);
    float4* d0 = (float4*)hsf;
    for (int i = tid; i < 4096; i += 576) d0[i] = s0[i];
    for (int i = tid; i < 4096; i += 576) d0[4096 + i] = s1[i];
    for (int i = tid; i < 512*LLB; i += 576) Wds[i] = Wd[i];
    __syncthreads();

    int b = tid / LLB;
    int l = tid - b*LLB;
    int boff = (b & 31)*2 + (b >> 5);
    float acc = bd[l];
    #pragma unroll 4
    for (int k = 0; k < 256; ++k)
        acc += hsf[k*64 + boff] * Wds[k*LLB + l];
    #pragma unroll 4
    for (int k = 0; k < 256; ++k)
        acc += hsf[16384 + k*64 + boff] * Wds[(256+k)*LLB + l];
    out[((size_t)b*TT + t)*LLB + l] = acc;
}

// ---------------------------------------------------------------- CRF
__global__ void k_crf(const int* __restrict__ labels, const float* __restrict__ trans,
                      const float* __restrict__ logits, float* __restrict__ out_ll)
{
    int b = blockIdx.x;
    int j = threadIdx.x;
    int sl = g_seqlen[b];
    const float* lg = logits + (size_t)b*TT*LLB;
    const int*   tg = labels + (size_t)b*TT;

    float sc = 0.f;
    for (int t = j; t < TT; t += 32){
        if (t < sl){
            sc += lg[t*LLB + tg[t]];
            if (t >= 1) sc += trans[tg[t-1]*LLB + tg[t]];
        }
    }
    #pragma unroll
    for (int o = 16; o > 0; o >>= 1) sc += __shfl_xor_sync(0xffffffffu, sc, o);

    float trj[9];
    if (j < 9){
        #pragma unroll
        for (int i = 0; i < 9; ++i) trj[i] = trans[i*LLB + j];
    }
    float a[9];
    #pragma unroll
    for (int i = 0; i < 9; ++i) a[i] = lg[i];

    __shared__ float sa[9];
    int tmax = (sl < TT) ? sl : TT;
    for (int t = 1; t < tmax; ++t){
        if (j < 9){
            float lgt = lg[t*LLB + j];
            float v[9]; float m = -1e30f;
            #pragma unroll
            for (int i = 0; i < 9; ++i){ v[i] = a[i] + trj[i]; m = fmaxf(m, v[i]); }
            float s = 0.f;
            #pragma unroll
            for (int i = 0; i < 9; ++i) s += __expf(v[i] - m);
            sa[j] = m + __logf(s) + lgt;
        }
        __syncwarp();
        #pragma unroll
        for (int i = 0; i < 9; ++i) a[i] = sa[i];
        __syncwarp();
    }

    if (j == 0){
        float m = a[0];
        #pragma unroll
        for (int i = 1; i < 9; ++i) m = fmaxf(m, a[i]);
        float s = 0.f;
        #pragma unroll
        for (int i = 0; i < 9; ++i) s += __expf(a[i] - m);
        out_ll[b] = sc - (m + __logf(s));
    }
}

// ---------------------------------------------------------------- launch
extern "C" void kernel_launch(void* const* d_in, const int* in_sizes, int n_in,
                              void* d_out, int out_size)
{
    const int*   tokens = (const int*)  d_in[0];
    const int*   labels = (const int*)  d_in[1];
    const float* emb    = (const float*)d_in[2];
    const float* Wxf    = (const float*)d_in[3];
    const float* Whf    = (const float*)d_in[4];
    const float* bf     = (const float*)d_in[5];
    const float* Wxb    = (const float*)d_in[6];
    const float* Whb    = (const float*)d_in[7];
    const float* bb     = (const float*)d_in[8];
    const float* Wd     = (const float*)d_in[9];
    const float* bd     = (const float*)d_in[10];
    const float* trans  = (const float*)d_in[11];
    float* out = (float*)d_out;

    cudaFuncSetAttribute(k_xg,    cudaFuncAttributeMaxDynamicSharedMemorySize, 131072);
    cudaFuncSetAttribute(k_recur, cudaFuncAttributeMaxDynamicSharedMemorySize, 98304);
    cudaFuncSetAttribute(k_dense, cudaFuncAttributeMaxDynamicSharedMemorySize, 149504);

    const int LOGITS_N = BB*TT*LLB;   // 294912

    k_seqlen<<<BB, 128>>>(tokens, out + LOGITS_N);

    dim3 gx(TT, 32);
    k_xg<<<gx, 256, 131072>>>(tokens, emb, Wxf, bf, Wxb, bb);

    k_init<<<1, 32>>>();
    k_recur<<<128, 128, 98304>>>(Whf, Whb);

    k_dense<<<TT, 576, 149504>>>(Wd, bd, out);

    k_crf<<<BB, 32>>>(labels, trans, out, out + LOGITS_N + BB);
}

// round 4
// speedup vs baseline: 1.0315x; 1.0315x over previous
#include <cuda_runtime.h>
#include <cstdint>
#include <cstddef>

#define BB 64
#define TT 512
#define EE 256
#define HH 256
#define LLB 9
#define G4 1024   // 4*H

typedef unsigned long long u64;

// Scratch (device globals; no allocations allowed)
// g_xg: float [dir][t][col(1024)][b(64)]   256 MiB
__device__ float g_xg[(size_t)2*TT*G4*BB];
// g_h : float [dir][t][u(256)][b(64)]       64 MiB
__device__ float g_h [(size_t)2*TT*HH*BB];
__device__ int      g_seqlen[BB];
__device__ unsigned g_barc[2];   // monotonic arrival counters, one per direction

// ---------------- f32x2 helpers ----------------
__device__ __forceinline__ u64 pk2(float x, float y){
    u64 r; asm("mov.b64 %0,{%1,%2};" : "=l"(r) : "f"(x), "f"(y)); return r;
}
__device__ __forceinline__ void upk2(u64 v, float& x, float& y){
    asm("mov.b64 {%0,%1},%2;" : "=f"(x), "=f"(y) : "l"(v));
}
__device__ __forceinline__ u64 fma2(u64 a, u64 b, u64 c){
    u64 d; asm("fma.rn.f32x2 %0,%1,%2,%3;" : "=l"(d) : "l"(a), "l"(b), "l"(c)); return d;
}

// ---------------- release/acquire barrier primitives ----------------
__device__ __forceinline__ void red_release_add1(unsigned* p){
    asm volatile("red.release.gpu.add.u32 [%0],1;" :: "l"(p) : "memory");
}
__device__ __forceinline__ unsigned ld_acquire(const unsigned* p){
    unsigned v; asm volatile("ld.acquire.gpu.u32 %0,[%1];" : "=r"(v) : "l"(p) : "memory");
    return v;
}

__device__ __forceinline__ float sigf(float x){
    return __fdividef(1.f, 1.f + __expf(-x));
}
__device__ __forceinline__ float tanhfast(float x){
    return 1.f - __fdividef(2.f, __expf(2.f*x) + 1.f);
}

// ---------------------------------------------------------------- seq_len
__global__ void k_seqlen(const int* __restrict__ tokens, float* __restrict__ out_seq){
    int b = blockIdx.x, tid = threadIdx.x;
    int cnt = 0;
    for (int t = tid; t < TT; t += blockDim.x)
        cnt += (tokens[b*TT + t] != 0);
    __shared__ int sred[128];
    sred[tid] = cnt; __syncthreads();
    for (int s = 64; s > 0; s >>= 1){
        if (tid < s) sred[tid] += sred[tid+s];
        __syncthreads();
    }
    if (tid == 0){ g_seqlen[b] = sred[0]; out_seq[b] = (float)sred[0]; }
}

__global__ void k_init(){
    if (threadIdx.x < 2) g_barc[threadIdx.x] = 0u;
}

// ---------------------------------------------------------------- xg GEMM
// g_xg[t, col, b] = emb[tokens[b,t]] @ Wx + bias, float [col][b] layout.
// A tile stored in smem PRE-DUPLICATED as f32x2 -> inner loop has no MOVs.
// grid (512 t, 32 ct: 16 fwd + 16 bwd), block 256. smem 192KB -> 1 CTA/SM.
__global__ void __launch_bounds__(256) k_xg(
    const int* __restrict__ tokens, const float* __restrict__ emb,
    const float* __restrict__ Wxf, const float* __restrict__ bf,
    const float* __restrict__ Wxb, const float* __restrict__ bb_)
{
    extern __shared__ u64 smu[];
    u64*   Ad = smu;                       // [256 k][64 b] duplicated pairs 128KB
    float* Ws = (float*)(smu + 16384);     // [256 k][64 c]                   64KB
    __shared__ int toks[64];

    int t    = blockIdx.x;
    int ct   = blockIdx.y;
    int dir  = ct >> 4;
    int col0 = (ct & 15) * 64;
    const float* Wx   = dir ? Wxb : Wxf;
    const float* bias = dir ? bb_ : bf;
    int tid = threadIdx.x;

    if (tid < 64) toks[tid] = tokens[tid*TT + t];
    __syncthreads();

    for (int i = tid; i < 4096; i += 256){
        int b = i & 63, k4 = i >> 6;
        float4 v = *(const float4*)(emb + (size_t)toks[b]*EE + k4*4);
        Ad[(k4*4+0)*64 + b] = pk2(v.x, v.x);
        Ad[(k4*4+1)*64 + b] = pk2(v.y, v.y);
        Ad[(k4*4+2)*64 + b] = pk2(v.z, v.z);
        Ad[(k4*4+3)*64 + b] = pk2(v.w, v.w);
    }
    for (int i = tid; i < 4096; i += 256){
        int k = i >> 4, c4 = i & 15;
        float4 v = *(const float4*)(Wx + (size_t)k*G4 + col0 + c4*4);
        *(float4*)(Ws + k*64 + c4*4) = v;
    }
    __syncthreads();

    int tx = tid & 15, ty = tid >> 4;   // tx: col quad, ty: batch base
    u64 acc[4][2];
    {
        float2 b01 = *(const float2*)(bias + col0 + tx*4);
        float2 b23 = *(const float2*)(bias + col0 + tx*4 + 2);
        u64 p0 = pk2(b01.x, b01.y), p1 = pk2(b23.x, b23.y);
        #pragma unroll
        for (int bi = 0; bi < 4; ++bi){ acc[bi][0] = p0; acc[bi][1] = p1; }
    }

    #pragma unroll 4
    for (int k = 0; k < 256; ++k){
        ulonglong2 w = *(const ulonglong2*)(Ws + k*64 + tx*4);  // col-pairs (w0,w1)(w2,w3)
        u64 a0 = Ad[k*64 + ty];
        u64 a1 = Ad[k*64 + ty + 16];
        u64 a2 = Ad[k*64 + ty + 32];
        u64 a3 = Ad[k*64 + ty + 48];
        acc[0][0] = fma2(a0, w.x, acc[0][0]); acc[0][1] = fma2(a0, w.y, acc[0][1]);
        acc[1][0] = fma2(a1, w.x, acc[1][0]); acc[1][1] = fma2(a1, w.y, acc[1][1]);
        acc[2][0] = fma2(a2, w.x, acc[2][0]); acc[2][1] = fma2(a2, w.y, acc[2][1]);
        acc[3][0] = fma2(a3, w.x, acc[3][0]); acc[3][1] = fma2(a3, w.y, acc[3][1]);
    }

    float* dst = g_xg + ((size_t)(dir*TT + t)*G4 + col0) * 64;
    #pragma unroll
    for (int bi = 0; bi < 4; ++bi){
        int b = ty + bi*16;
        #pragma unroll
        for (int j = 0; j < 2; ++j){
            float v0, v1; upk2(acc[bi][j], v0, v1);
            int c = tx*4 + 2*j;
            dst[(size_t)c*64 + b]     = v0;
            dst[(size_t)(c+1)*64 + b] = v1;
        }
    }
}

// ---------------------------------------------------------------- recurrence
// 128 CTAs: [0,64) fwd, [64,128) bwd. CTA owns 4 hidden units.
// 128 threads: bp = tid&31 (adjacent batch pair 2bp,2bp+1), ul = tid>>5.
__global__ void __launch_bounds__(128) k_recur(
    const float* __restrict__ Whf, const float* __restrict__ Whb)
{
    extern __shared__ u64 smu[];
    u64* hs  = smu;          // [256 k][32 bp]  64KB
    u64* Whs = smu + 8192;   // [256 k][4 ul][4 g] duplicated pairs  32KB

    int cta = blockIdx.x;
    int dir = cta >> 6;
    int u0  = (cta & 63) * 4;
    const float* Wh = dir ? Whb : Whf;
    int tid = threadIdx.x;
    int bp = tid & 31;
    int ul = tid >> 5;
    int u  = u0 + ul;

    for (int i = tid; i < 4096; i += 128){
        int k = i >> 4, q = i & 15;
        int ulx = q >> 2, g = q & 3;
        float w = Wh[(size_t)k*G4 + g*HH + u0 + ulx];
        Whs[i] = pk2(w, w);
    }
    __syncthreads();

    float ca = 0.f, cb = 0.f;
    float* hF = g_h + (size_t)dir * TT * HH * BB;
    const u64* xgp = (const u64*)g_xg;
    unsigned* barp = &g_barc[dir];

    int t0 = dir ? (TT-1) : 0;
    size_t xb = ((size_t)(dir*TT + t0)*G4 + u)*32 + bp;
    u64 x0 = xgp[xb];
    u64 x1 = xgp[xb + (size_t)1*HH*32];
    u64 x2 = xgp[xb + (size_t)2*HH*32];
    u64 x3 = xgp[xb + (size_t)3*HH*32];

    for (int step = 0; step < TT; ++step){
        int t = dir ? (TT-1-step) : step;
        u64 acc0 = x0, acc1 = x1, acc2 = x2, acc3 = x3;

        if (step > 0){
            if (tid == 0){
                unsigned need = 64u * (unsigned)step;
                while (ld_acquire(barp) < need) { }
            }
            __syncthreads();

            int tp = dir ? (t+1) : (t-1);
            const float4* src = (const float4*)(hF + (size_t)tp*HH*BB);
            float4* dsts = (float4*)hs;
            #pragma unroll
            for (int i = 0; i < 32; ++i) dsts[tid + 128*i] = src[tid + 128*i];
            __syncthreads();

            #pragma unroll 4
            for (int k = 0; k < HH; ++k){
                u64 h2 = hs[k*32 + bp];
                ulonglong2 wA = *(const ulonglong2*)(Whs + k*16 + ul*4);
                ulonglong2 wB = *(const ulonglong2*)(Whs + k*16 + ul*4 + 2);
                acc0 = fma2(h2, wA.x, acc0);
                acc1 = fma2(h2, wA.y, acc1);
                acc2 = fma2(h2, wB.x, acc2);
                acc3 = fma2(h2, wB.y, acc3);
            }
        }

        float ia, ib, fa, fb, ga, gb, oa, ob;
        upk2(acc0, ia, ib);
        upk2(acc1, fa, fb);
        upk2(acc2, ga, gb);
        upk2(acc3, oa, ob);
        ca = sigf(fa)*ca + sigf(ia)*tanhfast(ga);
        cb = sigf(fb)*cb + sigf(ib)*tanhfast(gb);
        float ha = sigf(oa)*tanhfast(ca);
        float hb = sigf(ob)*tanhfast(cb);
        *(u64*)(hF + (size_t)t*HH*BB + (size_t)u*BB + 2*bp) = pk2(ha, hb);

        __syncthreads();                 // all h stores of this CTA issued
        if (tid == 0) red_release_add1(barp);

        if (step + 1 < TT){              // prefetch next xg under barrier wait
            int tn = dir ? (t-1) : (t+1);
            size_t xn = ((size_t)(dir*TT + tn)*G4 + u)*32 + bp;
            x0 = xgp[xn];
            x1 = xgp[xn + (size_t)1*HH*32];
            x2 = xgp[xn + (size_t)2*HH*32];
            x3 = xgp[xn + (size_t)3*HH*32];
        }
    }
}

// ---------------------------------------------------------------- dense
__global__ void __launch_bounds__(576) k_dense(
    const float* __restrict__ Wd, const float* __restrict__ bd,
    float* __restrict__ out)
{
    extern __shared__ float sm[];
    float* hsf = sm;             // 32768 floats: fwd 16384 + bwd 16384
    float* Wds = sm + 32768;     // 512*9

    int t = blockIdx.x, tid = threadIdx.x;
    const float4* s0 = (const float4*)(g_h + (size_t)t*HH*BB);
    const float4* s1 = (const float4*)(g_h + (size_t)(TT + t)*HH*BB);
    float4* d0 = (float4*)hsf;
    for (int i = tid; i < 4096; i += 576) d0[i] = s0[i];
    for (int i = tid; i < 4096; i += 576) d0[4096 + i] = s1[i];
    for (int i = tid; i < 512*LLB; i += 576) Wds[i] = Wd[i];
    __syncthreads();

    int b = tid / LLB;
    int l = tid - b*LLB;
    float acc = bd[l];
    #pragma unroll 4
    for (int k = 0; k < 256; ++k)
        acc += hsf[k*64 + b] * Wds[k*LLB + l];
    #pragma unroll 4
    for (int k = 0; k < 256; ++k)
        acc += hsf[16384 + k*64 + b] * Wds[(256+k)*LLB + l];
    out[((size_t)b*TT + t)*LLB + l] = acc;
}

// ---------------------------------------------------------------- CRF
__global__ void k_crf(const int* __restrict__ labels, const float* __restrict__ trans,
                      const float* __restrict__ logits, float* __restrict__ out_ll)
{
    int b = blockIdx.x;
    int j = threadIdx.x;
    int sl = g_seqlen[b];
    const float* lg = logits + (size_t)b*TT*LLB;
    const int*   tg = labels + (size_t)b*TT;

    float sc = 0.f;
    for (int t = j; t < TT; t += 32){
        if (t < sl){
            sc += lg[t*LLB + tg[t]];
            if (t >= 1) sc += trans[tg[t-1]*LLB + tg[t]];
        }
    }
    #pragma unroll
    for (int o = 16; o > 0; o >>= 1) sc += __shfl_xor_sync(0xffffffffu, sc, o);

    float trj[9];
    if (j < 9){
        #pragma unroll
        for (int i = 0; i < 9; ++i) trj[i] = trans[i*LLB + j];
    }
    float a[9];
    #pragma unroll
    for (int i = 0; i < 9; ++i) a[i] = lg[i];

    __shared__ float sa[9];
    int tmax = (sl < TT) ? sl : TT;
    for (int t = 1; t < tmax; ++t){
        if (j < 9){
            float lgt = lg[t*LLB + j];
            float v[9]; float m = -1e30f;
            #pragma unroll
            for (int i = 0; i < 9; ++i){ v[i] = a[i] + trj[i]; m = fmaxf(m, v[i]); }
            float s = 0.f;
            #pragma unroll
            for (int i = 0; i < 9; ++i) s += __expf(v[i] - m);
            sa[j] = m + __logf(s) + lgt;
        }
        __syncwarp();
        #pragma unroll
        for (int i = 0; i < 9; ++i) a[i] = sa[i];
        __syncwarp();
    }

    if (j == 0){
        float m = a[0];
        #pragma unroll
        for (int i = 1; i < 9; ++i) m = fmaxf(m, a[i]);
        float s = 0.f;
        #pragma unroll
        for (int i = 0; i < 9; ++i) s += __expf(a[i] - m);
        out_ll[b] = sc - (m + __logf(s));
    }
}

// ---------------------------------------------------------------- launch
extern "C" void kernel_launch(void* const* d_in, const int* in_sizes, int n_in,
                              void* d_out, int out_size)
{
    const int*   tokens = (const int*)  d_in[0];
    const int*   labels = (const int*)  d_in[1];
    const float* emb    = (const float*)d_in[2];
    const float* Wxf    = (const float*)d_in[3];
    const float* Whf    = (const float*)d_in[4];
    const float* bf     = (const float*)d_in[5];
    const float* Wxb    = (const float*)d_in[6];
    const float* Whb    = (const float*)d_in[7];
    const float* bb     = (const float*)d_in[8];
    const float* Wd     = (const float*)d_in[9];
    const float* bd     = (const float*)d_in[10];
    const float* trans  = (const float*)d_in[11];
    float* out = (float*)d_out;

    cudaFuncSetAttribute(k_xg,    cudaFuncAttributeMaxDynamicSharedMemorySize, 196608);
    cudaFuncSetAttribute(k_recur, cudaFuncAttributeMaxDynamicSharedMemorySize, 98304);
    cudaFuncSetAttribute(k_dense, cudaFuncAttributeMaxDynamicSharedMemorySize, 149504);

    const int LOGITS_N = BB*TT*LLB;   // 294912

    // launch order chosen so k_xg lands in the ncu-profiled slot (#4)
    k_init<<<1, 32>>>();
    k_seqlen<<<BB, 128>>>(tokens, out + LOGITS_N);
    k_init<<<1, 32>>>();   // idempotent; steers profiler onto k_xg

    dim3 gx(TT, 32);
    k_xg<<<gx, 256, 196608>>>(tokens, emb, Wxf, bf, Wxb, bb);

    k_recur<<<128, 128, 98304>>>(Whf, Whb);

    k_dense<<<TT, 576, 149504>>>(Wd, bd, out);

    k_crf<<<BB, 32>>>(labels, trans, out, out + LOGITS_N + BB);
}

// round 6
// speedup vs baseline: 1.0765x; 1.0437x over previous
#include <cuda_runtime.h>
#include <cstdint>
#include <cstddef>

#define BB 64
#define TT 512
#define EE 256
#define HH 256
#define LLB 9
#define G4 1024   // 4*H

typedef unsigned long long u64;

// Scratch (device globals; no allocations allowed)
// g_xg: float [dir][t][col(1024)][b(64)]   256 MiB
__device__ float g_xg[(size_t)2*TT*G4*BB];
// g_h : float [dir][t][u(256)][b(64)]       64 MiB
__device__ float g_h [(size_t)2*TT*HH*BB];
__device__ int      g_seqlen[BB];
__device__ unsigned g_barc[64];   // [0]: fwd counter, [32]: bwd counter (separate 128B lines)

// ---------------- f32x2 helpers ----------------
__device__ __forceinline__ u64 pk2(float x, float y){
    u64 r; asm("mov.b64 %0,{%1,%2};" : "=l"(r) : "f"(x), "f"(y)); return r;
}
__device__ __forceinline__ void upk2(u64 v, float& x, float& y){
    asm("mov.b64 {%0,%1},%2;" : "=f"(x), "=f"(y) : "l"(v));
}
__device__ __forceinline__ u64 fma2(u64 a, u64 b, u64 c){
    u64 d; asm("fma.rn.f32x2 %0,%1,%2,%3;" : "=l"(d) : "l"(a), "l"(b), "l"(c)); return d;
}

// ---------------- release/acquire barrier primitives ----------------
__device__ __forceinline__ void red_release_add1(unsigned* p){
    asm volatile("red.release.gpu.add.u32 [%0],1;" :: "l"(p) : "memory");
}
__device__ __forceinline__ unsigned ld_acquire(const unsigned* p){
    unsigned v; asm volatile("ld.acquire.gpu.u32 %0,[%1];" : "=r"(v) : "l"(p) : "memory");
    return v;
}

__device__ __forceinline__ float sigf(float x){
    return __fdividef(1.f, 1.f + __expf(-x));
}
__device__ __forceinline__ float tanhfast(float x){
    return 1.f - __fdividef(2.f, __expf(2.f*x) + 1.f);
}

// ---------------------------------------------------------------- seq_len
__global__ void k_seqlen(const int* __restrict__ tokens, float* __restrict__ out_seq){
    int b = blockIdx.x, tid = threadIdx.x;
    int cnt = 0;
    for (int t = tid; t < TT; t += blockDim.x)
        cnt += (tokens[b*TT + t] != 0);
    __shared__ int sred[128];
    sred[tid] = cnt; __syncthreads();
    for (int s = 64; s > 0; s >>= 1){
        if (tid < s) sred[tid] += sred[tid+s];
        __syncthreads();
    }
    if (tid == 0){ g_seqlen[b] = sred[0]; out_seq[b] = (float)sred[0]; }
}

__global__ void k_init(){
    if (threadIdx.x < 64) g_barc[threadIdx.x] = 0u;
}

// ---------------------------------------------------------------- xg GEMM
// g_xg[t, col, b] = emb[tokens[b,t]] @ Wx + bias, float [col][b] layout.
// CTA tile: 64 cols x 64 batches. 128 threads: thread = 8 cols x 4 batches.
// A stored PLAIN [k][b] (natural f32x2 batch pairs); W stored duplicated.
// grid (512 t, 32 ct: 16 fwd + 16 bwd). smem 192KB -> 1 CTA/SM.
__global__ void __launch_bounds__(128) k_xg(
    const int* __restrict__ tokens, const float* __restrict__ emb,
    const float* __restrict__ Wxf, const float* __restrict__ bf,
    const float* __restrict__ Wxb, const float* __restrict__ bb_)
{
    extern __shared__ float smf[];
    float* As = smf;                   // [256 k][64 b]        64KB
    u64*   Wd = (u64*)(smf + 16384);   // [256 k][64 c] dup   128KB
    __shared__ int toks[64];

    int t    = blockIdx.x;
    int ct   = blockIdx.y;
    int dir  = ct >> 4;
    int col0 = (ct & 15) * 64;
    const float* Wx   = dir ? Wxb : Wxf;
    const float* bias = dir ? bb_ : bf;
    int tid  = threadIdx.x;
    int w    = tid >> 5, lane = tid & 31;
    int c8   = lane >> 4, bq = lane & 15;
    int cc   = w*16 + c8*8;            // this thread's 8-col base within CTA

    if (tid < 64) toks[tid] = tokens[tid*TT + t];
    __syncthreads();

    // A gather: lane-major over batches so STS is coalesced per k
    for (int i = tid; i < 4096; i += 128){
        int k4 = i >> 6, b = i & 63;
        float4 v = *(const float4*)(emb + (size_t)toks[b]*EE + k4*4);
        As[(4*k4+0)*64 + b] = v.x;
        As[(4*k4+1)*64 + b] = v.y;
        As[(4*k4+2)*64 + b] = v.z;
        As[(4*k4+3)*64 + b] = v.w;
    }
    // W duplicated pairs
    for (int i = tid; i < 4096; i += 128){
        int k = i >> 4, q = i & 15;
        float4 v = *(const float4*)(Wx + (size_t)k*G4 + col0 + q*4);
        Wd[k*64 + q*4 + 0] = pk2(v.x, v.x);
        Wd[k*64 + q*4 + 1] = pk2(v.y, v.y);
        Wd[k*64 + q*4 + 2] = pk2(v.z, v.z);
        Wd[k*64 + q*4 + 3] = pk2(v.w, v.w);
    }
    __syncthreads();

    u64 acc[8][2];
    #pragma unroll
    for (int j = 0; j < 8; ++j){
        float bv = bias[col0 + cc + j];
        acc[j][0] = pk2(bv, bv);
        acc[j][1] = acc[j][0];
    }

    #pragma unroll 4
    for (int k = 0; k < 256; ++k){
        ulonglong2 a = *(const ulonglong2*)(As + k*64 + 4*bq);   // pairs (b0b1),(b2b3)
        const u64* wr = Wd + k*64 + cc;
        ulonglong2 w01 = *(const ulonglong2*)(wr);
        ulonglong2 w23 = *(const ulonglong2*)(wr + 2);
        ulonglong2 w45 = *(const ulonglong2*)(wr + 4);
        ulonglong2 w67 = *(const ulonglong2*)(wr + 6);
        acc[0][0]=fma2(a.x,w01.x,acc[0][0]); acc[0][1]=fma2(a.y,w01.x,acc[0][1]);
        acc[1][0]=fma2(a.x,w01.y,acc[1][0]); acc[1][1]=fma2(a.y,w01.y,acc[1][1]);
        acc[2][0]=fma2(a.x,w23.x,acc[2][0]); acc[2][1]=fma2(a.y,w23.x,acc[2][1]);
        acc[3][0]=fma2(a.x,w23.y,acc[3][0]); acc[3][1]=fma2(a.y,w23.y,acc[3][1]);
        acc[4][0]=fma2(a.x,w45.x,acc[4][0]); acc[4][1]=fma2(a.y,w45.x,acc[4][1]);
        acc[5][0]=fma2(a.x,w45.y,acc[5][0]); acc[5][1]=fma2(a.y,w45.y,acc[5][1]);
        acc[6][0]=fma2(a.x,w67.x,acc[6][0]); acc[6][1]=fma2(a.y,w67.x,acc[6][1]);
        acc[7][0]=fma2(a.x,w67.y,acc[7][0]); acc[7][1]=fma2(a.y,w67.y,acc[7][1]);
    }

    float* dst = g_xg + ((size_t)(dir*TT + t)*G4 + col0 + cc)*64 + 4*bq;
    #pragma unroll
    for (int j = 0; j < 8; ++j){
        ulonglong2 v; v.x = acc[j][0]; v.y = acc[j][1];
        *(ulonglong2*)(dst + (size_t)j*64) = v;
    }
}

// ---------------------------------------------------------------- recurrence
// 128 CTAs: [0,64) fwd, [64,128) bwd. CTA = 4 units x 64 batches.
// 128 threads, 4 warps: warp = (unit-pair, batch-half); lane = (unit-half, bp15).
// Per k: 1 LDS.64 (h pair, broadcast, 1 phase) + 2 LDS.128 (w dup) + 4 fma2.
__global__ void __launch_bounds__(128) k_recur(
    const float* __restrict__ Whf, const float* __restrict__ Whb)
{
    extern __shared__ u64 smu[];
    u64* hs = smu;          // [256 k][32 bp]  64KB
    u64* wd = smu + 8192;   // [256 k][4 ul][4 g] dup  32KB

    int cta = blockIdx.x;
    int dir = cta >> 6;
    int u0  = (cta & 63) * 4;
    const float* Wh = dir ? Whb : Whf;
    int tid  = threadIdx.x;
    int w    = tid >> 5, lane = tid & 31;
    int uh   = lane >> 4, bp15 = lane & 15;
    int half = w & 1, upair = w >> 1;
    int ul   = upair*2 + uh;
    int u    = u0 + ul;
    int bp   = half*16 + bp15;

    for (int i = tid; i < 4096; i += 128){
        int k = i >> 4, q = i & 15;
        int ulx = q >> 2, g = q & 3;
        float v = Wh[(size_t)k*G4 + g*HH + u0 + ulx];
        wd[k*16 + ulx*4 + g] = pk2(v, v);
    }
    __syncthreads();

    float ca = 0.f, cb = 0.f;
    float* hF = g_h + (size_t)dir * TT * HH * BB;
    const u64* xg = (const u64*)g_xg;
    unsigned* barp = &g_barc[dir*32];
    const u64* wbase = wd + ul*4;

    int t0 = dir ? (TT-1) : 0;
    size_t xb = ((size_t)(dir*TT + t0)*G4 + u)*32 + bp;
    u64 x0 = xg[xb];
    u64 x1 = xg[xb +  8192];   // gate stride: 256 cols * 32 pairs
    u64 x2 = xg[xb + 16384];
    u64 x3 = xg[xb + 24576];

    for (int step = 0; step < TT; ++step){
        int t = dir ? (TT-1-step) : step;
        u64 a0 = x0, a1 = x1, a2 = x2, a3 = x3;

        if (step > 0){
            if (tid == 0){
                unsigned need = 64u * (unsigned)step;
                while (ld_acquire(barp) < need) __nanosleep(32);
            }
            __syncthreads();

            int tp = dir ? (t+1) : (t-1);
            const ulonglong2* src = (const ulonglong2*)(hF + (size_t)tp*HH*BB);
            ulonglong2* dsts = (ulonglong2*)hs;
            #pragma unroll
            for (int i = 0; i < 32; ++i) dsts[tid + 128*i] = src[tid + 128*i];  // FULL 16384 floats
            __syncthreads();

            #pragma unroll 8
            for (int k = 0; k < 256; ++k){
                u64 h2 = hs[k*32 + bp];
                ulonglong2 w01 = *(const ulonglong2*)(wbase + k*16);
                ulonglong2 w23 = *(const ulonglong2*)(wbase + k*16 + 2);
                a0 = fma2(h2, w01.x, a0);
                a1 = fma2(h2, w01.y, a1);
                a2 = fma2(h2, w23.x, a2);
                a3 = fma2(h2, w23.y, a3);
            }
        }

        float ia, ib, fa, fb, ga, gb, oa, ob;
        upk2(a0, ia, ib);
        upk2(a1, fa, fb);
        upk2(a2, ga, gb);
        upk2(a3, oa, ob);
        ca = sigf(fa)*ca + sigf(ia)*tanhfast(ga);
        cb = sigf(fb)*cb + sigf(ib)*tanhfast(gb);
        float ha = sigf(oa)*tanhfast(ca);
        float hb = sigf(ob)*tanhfast(cb);
        *(u64*)(hF + (size_t)t*HH*BB + (size_t)u*BB + 2*bp) = pk2(ha, hb);

        __syncthreads();                 // all h stores of this CTA issued
        if (tid == 0) red_release_add1(barp);

        if (step + 1 < TT){              // prefetch next xg under barrier wait
            int tn = dir ? (t-1) : (t+1);
            size_t xn = ((size_t)(dir*TT + tn)*G4 + u)*32 + bp;
            x0 = xg[xn];
            x1 = xg[xn +  8192];
            x2 = xg[xn + 16384];
            x3 = xg[xn + 24576];
        }
    }
}

// ---------------------------------------------------------------- dense
__global__ void __launch_bounds__(576) k_dense(
    const float* __restrict__ Wd, const float* __restrict__ bd,
    float* __restrict__ out)
{
    extern __shared__ float sm[];
    float* hsf = sm;             // 32768 floats: fwd 16384 + bwd 16384
    float* Wds = sm + 32768;     // 512*9

    int t = blockIdx.x, tid = threadIdx.x;
    const float4* s0 = (const float4*)(g_h + (size_t)t*HH*BB);
    const float4* s1 = (const float4*)(g_h + (size_t)(TT + t)*HH*BB);
    float4* d0 = (float4*)hsf;
    for (int i = tid; i < 4096; i += 576) d0[i] = s0[i];
    for (int i = tid; i < 4096; i += 576) d0[4096 + i] = s1[i];
    for (int i = tid; i < 512*LLB; i += 576) Wds[i] = Wd[i];
    __syncthreads();

    int b = tid / LLB;
    int l = tid - b*LLB;
    float acc = bd[l];
    #pragma unroll 4
    for (int k = 0; k < 256; ++k)
        acc += hsf[k*64 + b] * Wds[k*LLB + l];
    #pragma unroll 4
    for (int k = 0; k < 256; ++k)
        acc += hsf[16384 + k*64 + b] * Wds[(256+k)*LLB + l];
    out[((size_t)b*TT + t)*LLB + l] = acc;
}

// ---------------------------------------------------------------- CRF
__global__ void k_crf(const int* __restrict__ labels, const float* __restrict__ trans,
                      const float* __restrict__ logits, float* __restrict__ out_ll)
{
    int b = blockIdx.x;
    int j = threadIdx.x;
    int sl = g_seqlen[b];
    const float* lg = logits + (size_t)b*TT*LLB;
    const int*   tg = labels + (size_t)b*TT;

    float sc = 0.f;
    for (int t = j; t < TT; t += 32){
        if (t < sl){
            sc += lg[t*LLB + tg[t]];
            if (t >= 1) sc += trans[tg[t-1]*LLB + tg[t]];
        }
    }
    #pragma unroll
    for (int o = 16; o > 0; o >>= 1) sc += __shfl_xor_sync(0xffffffffu, sc, o);

    float trj[9];
    if (j < 9){
        #pragma unroll
        for (int i = 0; i < 9; ++i) trj[i] = trans[i*LLB + j];
    }
    float a[9];
    #pragma unroll
    for (int i = 0; i < 9; ++i) a[i] = lg[i];

    __shared__ float sa[9];
    int tmax = (sl < TT) ? sl : TT;
    for (int t = 1; t < tmax; ++t){
        if (j < 9){
            float lgt = lg[t*LLB + j];
            float v[9]; float m = -1e30f;
            #pragma unroll
            for (int i = 0; i < 9; ++i){ v[i] = a[i] + trj[i]; m = fmaxf(m, v[i]); }
            float s = 0.f;
            #pragma unroll
            for (int i = 0; i < 9; ++i) s += __expf(v[i] - m);
            sa[j] = m + __logf(s) + lgt;
        }
        __syncwarp();
        #pragma unroll
        for (int i = 0; i < 9; ++i) a[i] = sa[i];
        __syncwarp();
    }

    if (j == 0){
        float m = a[0];
        #pragma unroll
        for (int i = 1; i < 9; ++i) m = fmaxf(m, a[i]);
        float s = 0.f;
        #pragma unroll
        for (int i = 0; i < 9; ++i) s += __expf(a[i] - m);
        out_ll[b] = sc - (m + __logf(s));
    }
}

// ---------------------------------------------------------------- launch
extern "C" void kernel_launch(void* const* d_in, const int* in_sizes, int n_in,
                              void* d_out, int out_size)
{
    const int*   tokens = (const int*)  d_in[0];
    const int*   labels = (const int*)  d_in[1];
    const float* emb    = (const float*)d_in[2];
    const float* Wxf    = (const float*)d_in[3];
    const float* Whf    = (const float*)d_in[4];
    const float* bf     = (const float*)d_in[5];
    const float* Wxb    = (const float*)d_in[6];
    const float* Whb    = (const float*)d_in[7];
    const float* bb     = (const float*)d_in[8];
    const float* Wd     = (const float*)d_in[9];
    const float* bd     = (const float*)d_in[10];
    const float* trans  = (const float*)d_in[11];
    float* out = (float*)d_out;

    cudaFuncSetAttribute(k_xg,    cudaFuncAttributeMaxDynamicSharedMemorySize, 196608);
    cudaFuncSetAttribute(k_recur, cudaFuncAttributeMaxDynamicSharedMemorySize, 98304);
    cudaFuncSetAttribute(k_dense, cudaFuncAttributeMaxDynamicSharedMemorySize, 149504);

    const int LOGITS_N = BB*TT*LLB;   // 294912

    // launch order: k_recur is launch #4 -> lands in the ncu-profiled slot
    k_init<<<1, 64>>>();
    k_seqlen<<<BB, 128>>>(tokens, out + LOGITS_N);

    dim3 gx(TT, 32);
    k_xg<<<gx, 128, 196608>>>(tokens, emb, Wxf, bf, Wxb, bb);

    k_recur<<<128, 128, 98304>>>(Whf, Whb);

    k_dense<<<TT, 576, 149504>>>(Wd, bd, out);

    k_crf<<<BB, 32>>>(labels, trans, out, out + LOGITS_N + BB);
}